// round 1
// baseline (speedup 1.0000x reference)
#include <cuda_runtime.h>
#include <math.h>

// Problem constants
#define BN_   256   // batch
#define TN_   256   // time steps
#define DN_   300   // input dim
#define HN_   512   // hidden
#define KTOT  812   // 300 + 512 fused K (x_t ++ h_{t-1})
#define FOURH 2048  // 4*H

// ---------------- scratch (device globals; no allocation allowed) ----------
__device__ float g_c[4][BN_][HN_];        // cell state per seq (p_fw,p_bw,h_fw,h_bw)
__device__ float g_h[2][4][BN_][HN_];     // double-buffered hidden state
__device__ float g_x [BN_ * FOURH];       // concat(c) -> MLP input
__device__ float g_m1[BN_ * 1024];
__device__ float g_m2[BN_ * 1024];
__device__ float g_m3[BN_ * 1024];

struct StepArgs {
    const float* x[4];     // [B,T,D]
    const int*   len[4];   // [B]
    const float* Wx[4];    // [300,2048]
    const float* Wh[4];    // [512,2048]
    const float* bias[4];  // [2048]
};

__device__ __forceinline__ float sigmoidf_(float v) { return 1.0f / (1.0f + expf(-v)); }

// ---------------- init: zero c and h ---------------------------------------
__global__ void zero_state_kernel() {
    int i = blockIdx.x * blockDim.x + threadIdx.x;
    float* c = &g_c[0][0][0];
    float* h = &g_h[0][0][0][0];
    if (i < 4 * BN_ * HN_)     c[i] = 0.0f;
    if (i < 2 * 4 * BN_ * HN_) h[i] = 0.0f;
}

// ---------------- fused LSTM step: z = [x_t ; h] @ [Wx;Wh] + b, gates ------
// Block tile: 64 batch rows x 64 hidden units x 4 gates. 256 threads,
// each computes 4(batch) x 4(hidden) x 4(gate) outputs.
#define BMT 64
#define BUT 64
#define KT  16

__global__ __launch_bounds__(256) void lstm_step_kernel(StepArgs p, int s) {
    const int seq = blockIdx.z;          // 0:p_fw 1:p_bw 2:h_fw 3:h_bw
    const int rev = seq & 1;
    const int t   = rev ? (TN_ - 1 - s) : s;
    const int b0  = blockIdx.y * BMT;
    const int u0  = blockIdx.x * BUT;

    const float* __restrict__ x   = p.x[seq];
    const float* __restrict__ Wx  = p.Wx[seq];
    const float* __restrict__ Wh  = p.Wh[seq];
    const float* __restrict__ hin = &g_h[s & 1][seq][0][0];
    float*       __restrict__ hout = &g_h[(s + 1) & 1][seq][0][0];
    float*       __restrict__ cbuf = &g_c[seq][0][0];

    __shared__ float As[KT][BMT];        // [k][row]
    __shared__ float Bs[4][KT][BUT];     // [gate][k][col]

    const int tid = threadIdx.x;         // 0..255
    const int rr  = tid >> 4;            // 0..15
    const int cc  = tid & 15;            // 0..15
    const int r0  = rr * 4;
    const int ut0 = cc * 4;

    float acc[4][4][4];                  // [gate][row][col]
    #pragma unroll
    for (int g = 0; g < 4; g++)
        #pragma unroll
        for (int r = 0; r < 4; r++)
            #pragma unroll
            for (int u = 0; u < 4; u++) acc[g][r][u] = 0.0f;

    for (int k0 = 0; k0 < KTOT; k0 += KT) {
        // ---- load A tile: 64 rows x 16 k (x_t for k<300, h for k>=300) ----
        {
            int r  = tid >> 2;                 // 0..63
            int kq = (tid & 3) * 4;            // 0,4,8,12
            int b  = b0 + r;
            #pragma unroll
            for (int i = 0; i < 4; i++) {
                int k = k0 + kq + i;
                float v = 0.0f;
                if (k < KTOT) {
                    v = (k < DN_) ? x[(b * TN_ + t) * DN_ + k]
                                  : hin[b * HN_ + (k - DN_)];
                }
                As[kq + i][r] = v;
            }
        }
        // ---- load B tile: 4 gates x 16 k x 64 cols (float4 each) ----------
        {
            #pragma unroll
            for (int q = 0; q < 4; q++) {
                int id  = tid + 256 * q;       // 0..1023
                int g   = id >> 8;
                int rem = id & 255;
                int kk  = rem >> 4;
                int uu  = (rem & 15) * 4;
                int k   = k0 + kk;
                float4 v = make_float4(0.f, 0.f, 0.f, 0.f);
                if (k < KTOT) {
                    const float* W = (k < DN_) ? (Wx + k * FOURH)
                                               : (Wh + (k - DN_) * FOURH);
                    v = *(const float4*)(W + g * HN_ + u0 + uu);
                }
                *(float4*)&Bs[g][kk][uu] = v;
            }
        }
        __syncthreads();

        #pragma unroll
        for (int kk = 0; kk < KT; kk++) {
            float4 a4 = *(const float4*)&As[kk][r0];
            float av[4] = {a4.x, a4.y, a4.z, a4.w};
            #pragma unroll
            for (int g = 0; g < 4; g++) {
                float4 b4 = *(const float4*)&Bs[g][kk][ut0];
                float bv[4] = {b4.x, b4.y, b4.z, b4.w};
                #pragma unroll
                for (int r = 0; r < 4; r++)
                    #pragma unroll
                    for (int u = 0; u < 4; u++)
                        acc[g][r][u] = fmaf(av[r], bv[u], acc[g][r][u]);
            }
        }
        __syncthreads();
    }

    // ---- epilogue: gates + masked state update ----------------------------
    const float* __restrict__ bias = p.bias[seq];
    const int*   __restrict__ len  = p.len[seq];
    #pragma unroll
    for (int r = 0; r < 4; r++) {
        int  b = b0 + r0 + r;
        bool m = (t < len[b]);
        #pragma unroll
        for (int u = 0; u < 4; u++) {
            int uc = u0 + ut0 + u;
            float iv = acc[0][r][u] + bias[0 * HN_ + uc];
            float jv = acc[1][r][u] + bias[1 * HN_ + uc];
            float fv = acc[2][r][u] + bias[2 * HN_ + uc];
            float ov = acc[3][r][u] + bias[3 * HN_ + uc];
            float c_old = cbuf[b * HN_ + uc];
            float h_old = hin[b * HN_ + uc];
            float nc = c_old * sigmoidf_(fv + 1.0f) + sigmoidf_(iv) * tanhf(jv);
            float nh = tanhf(nc) * sigmoidf_(ov);
            cbuf[b * HN_ + uc] = m ? nc : c_old;
            hout[b * HN_ + uc] = m ? nh : h_old;
        }
    }
}

// ---------------- gather concat(c_pfw, c_pbw, c_hfw, c_hbw) -> g_x ---------
__global__ void gather_x_kernel() {
    int i = blockIdx.x * blockDim.x + threadIdx.x;   // 256*2048
    if (i >= BN_ * FOURH) return;
    int b   = i >> 11;
    int col = i & 2047;
    int seq = col >> 9;
    int u   = col & 511;
    g_x[i] = g_c[seq][b][u];
}

// ---------------- generic MLP GEMM + tanh ----------------------------------
// out[M,N] = tanh(A[M,K] @ W[K,N] + bias[N]);  M=256.  layer selects buffers.
__global__ __launch_bounds__(256) void mlp_gemm_kernel(const float* __restrict__ W,
                                                       const float* __restrict__ bias,
                                                       int layer) {
    const float* A; float* C; int K, N;
    if (layer == 1)      { A = g_x;  C = g_m1; K = 2048; N = 1024; }
    else if (layer == 2) { A = g_m1; C = g_m2; K = 1024; N = 1024; }
    else                 { A = g_m2; C = g_m3; K = 1024; N = 1024; }

    const int m0 = blockIdx.y * BMT;
    const int n0 = blockIdx.x * BUT;

    __shared__ float As[KT][BMT];
    __shared__ float Bs[KT][BUT];

    const int tid = threadIdx.x;
    const int rr  = tid >> 4;
    const int cc  = tid & 15;
    const int r0  = rr * 4;
    const int nt0 = cc * 4;

    float acc[4][4];
    #pragma unroll
    for (int r = 0; r < 4; r++)
        #pragma unroll
        for (int u = 0; u < 4; u++) acc[r][u] = 0.0f;

    for (int k0 = 0; k0 < K; k0 += KT) {
        {
            int r  = tid >> 2;
            int kq = (tid & 3) * 4;
            #pragma unroll
            for (int i = 0; i < 4; i++) {
                int k = k0 + kq + i;
                As[kq + i][r] = (k < K) ? A[(m0 + r) * K + k] : 0.0f;
            }
        }
        {
            int kk = tid >> 4;
            int uu = (tid & 15) * 4;
            int k  = k0 + kk;
            float4 v = make_float4(0.f, 0.f, 0.f, 0.f);
            if (k < K) v = *(const float4*)(W + k * N + n0 + uu);
            *(float4*)&Bs[kk][uu] = v;
        }
        __syncthreads();

        #pragma unroll
        for (int kk = 0; kk < KT; kk++) {
            float4 a4 = *(const float4*)&As[kk][r0];
            float av[4] = {a4.x, a4.y, a4.z, a4.w};
            float4 b4 = *(const float4*)&Bs[kk][nt0];
            float bv[4] = {b4.x, b4.y, b4.z, b4.w};
            #pragma unroll
            for (int r = 0; r < 4; r++)
                #pragma unroll
                for (int u = 0; u < 4; u++)
                    acc[r][u] = fmaf(av[r], bv[u], acc[r][u]);
        }
        __syncthreads();
    }

    #pragma unroll
    for (int r = 0; r < 4; r++)
        #pragma unroll
        for (int u = 0; u < 4; u++) {
            int n = n0 + nt0 + u;
            C[(m0 + r0 + r) * N + n] = tanhf(acc[r][u] + bias[n]);
        }
}

// ---------------- final logits: [256,1024] @ [1024,3] + b4 -----------------
__global__ void final_logits_kernel(const float* __restrict__ W4,
                                    const float* __restrict__ b4,
                                    float* __restrict__ out) {
    int b    = blockIdx.x;
    int w    = threadIdx.x >> 5;   // 0..2 -> output column
    int lane = threadIdx.x & 31;
    if (w >= 3) return;
    float sum = 0.0f;
    for (int k = lane; k < 1024; k += 32)
        sum += g_m3[b * 1024 + k] * W4[k * 3 + w];
    #pragma unroll
    for (int off = 16; off; off >>= 1)
        sum += __shfl_down_sync(0xffffffff, sum, off);
    if (lane == 0) out[b * 3 + w] = sum + b4[w];
}

// ---------------- launcher -------------------------------------------------
extern "C" void kernel_launch(void* const* d_in, const int* in_sizes, int n_in,
                              void* d_out, int out_size) {
    const float* premises   = (const float*)d_in[0];
    const float* hypotheses = (const float*)d_in[1];
    const int*   plen       = (const int*)d_in[2];
    const int*   hlen       = (const int*)d_in[3];

    StepArgs sp;
    sp.x[0] = premises;   sp.x[1] = premises;
    sp.x[2] = hypotheses; sp.x[3] = hypotheses;
    sp.len[0] = plen; sp.len[1] = plen;
    sp.len[2] = hlen; sp.len[3] = hlen;
    // weights: p_fw(4,5,6) p_bw(7,8,9) h_fw(10,11,12) h_bw(13,14,15)
    for (int i = 0; i < 4; i++) {
        sp.Wx[i]   = (const float*)d_in[4 + 3 * i + 0];
        sp.Wh[i]   = (const float*)d_in[4 + 3 * i + 1];
        sp.bias[i] = (const float*)d_in[4 + 3 * i + 2];
    }
    const float* W1 = (const float*)d_in[16];
    const float* b1 = (const float*)d_in[17];
    const float* W2 = (const float*)d_in[18];
    const float* b2 = (const float*)d_in[19];
    const float* W3 = (const float*)d_in[20];
    const float* b3 = (const float*)d_in[21];
    const float* W4 = (const float*)d_in[22];
    const float* b4 = (const float*)d_in[23];
    float* out = (float*)d_out;

    zero_state_kernel<<<(2 * 4 * BN_ * HN_ + 255) / 256, 256>>>();

    dim3 grid(HN_ / BUT, BN_ / BMT, 4);   // (8, 4, 4) = 128 blocks
    for (int s = 0; s < TN_; s++)
        lstm_step_kernel<<<grid, 256>>>(sp, s);

    gather_x_kernel<<<(BN_ * FOURH + 255) / 256, 256>>>();

    mlp_gemm_kernel<<<dim3(1024 / BUT, BN_ / BMT), 256>>>(W1, b1, 1);
    mlp_gemm_kernel<<<dim3(1024 / BUT, BN_ / BMT), 256>>>(W2, b2, 2);
    mlp_gemm_kernel<<<dim3(1024 / BUT, BN_ / BMT), 256>>>(W3, b3, 3);

    final_logits_kernel<<<BN_, 96>>>(W4, b4, out);
}

// round 3
// speedup vs baseline: 2.7560x; 2.7560x over previous
#include <cuda_runtime.h>
#include <cuda_fp16.h>
#include <math.h>
#include <stdint.h>

// ---------------------------------------------------------------------------
// Problem constants
#define BN_   256   // batch
#define TN_   256   // time steps
#define DN_   300   // input dim
#define HN_   512   // hidden
#define XPAD  320   // x padded to 320 (5 chunks of 64)
#define KPAD  832   // 320 + 512
#define NCHUNK 13   // 832 / 64
#define FOURH 2048

// ---------------------------------------------------------------------------
// Scratch (device globals) — inputs pre-split into fp16 hi/lo arrays
__device__ __half g_xhi[2ll * BN_ * TN_ * XPAD];
__device__ __half g_xlo[2ll * BN_ * TN_ * XPAD];
__device__ __half g_whi[4ll * FOURH * KPAD];
__device__ __half g_wlo[4ll * FOURH * KPAD];
__device__ float  g_bp [4 * FOURH];                 // permuted bias
__device__ __half g_hhi[2ll * 4 * BN_ * HN_];       // double-buffered h hi
__device__ __half g_hlo[2ll * 4 * BN_ * HN_];       // double-buffered h lo
__device__ float  g_c  [4][BN_][HN_];               // cell state
__device__ float  g_x  [BN_ * FOURH];               // concat c -> MLP input
__device__ float  g_m1[BN_ * 1024];
__device__ float  g_m2[BN_ * 1024];
__device__ float  g_m3[BN_ * 1024];

__device__ __forceinline__ float sigmoidf_(float v) { return 1.0f / (1.0f + expf(-v)); }

__device__ __forceinline__ uint32_t smem_u32(const void* p) {
    uint32_t a;
    asm("{ .reg .u64 t; cvta.to.shared.u64 t, %1; cvt.u32.u64 %0, t; }" : "=r"(a) : "l"(p));
    return a;
}
__device__ __forceinline__ void cp16(uint32_t dst, const void* src) {
    asm volatile("cp.async.cg.shared.global [%0], [%1], 16;" :: "r"(dst), "l"(src));
}
#define CP_COMMIT() asm volatile("cp.async.commit_group;" ::: "memory")
#define CP_WAIT(N)  asm volatile("cp.async.wait_group %0;" :: "n"(N) : "memory")

#define LDSM_X4(r0, r1, r2, r3, addr)                                         \
    asm volatile("ldmatrix.sync.aligned.m8n8.x4.shared.b16 {%0,%1,%2,%3}, [%4];" \
        : "=r"(r0), "=r"(r1), "=r"(r2), "=r"(r3) : "r"(addr))

#define MMA16816(d, a, b)                                                     \
    asm volatile("mma.sync.aligned.m16n8k16.row.col.f32.f16.f16.f32 "         \
        "{%0,%1,%2,%3}, {%4,%5,%6,%7}, {%8,%9}, {%0,%1,%2,%3};"               \
        : "+f"((d)[0]), "+f"((d)[1]), "+f"((d)[2]), "+f"((d)[3])              \
        : "r"((a)[0]), "r"((a)[1]), "r"((a)[2]), "r"((a)[3]),                 \
          "r"((b)[0]), "r"((b)[1]))

// ---------------------------------------------------------------------------
// One-time converts
__global__ void zero_state_kernel() {
    int i = blockIdx.x * blockDim.x + threadIdx.x;
    if (i < 2 * 4 * BN_ * HN_) { g_hhi[i] = __float2half(0.f); g_hlo[i] = __float2half(0.f); }
    if (i < 4 * BN_ * HN_)     (&g_c[0][0][0])[i] = 0.0f;
}

__global__ void conv_x_kernel(const float* __restrict__ prem, const float* __restrict__ hyp) {
    long long i = (long long)blockIdx.x * blockDim.x + threadIdx.x;
    if (i >= 2ll * BN_ * TN_ * XPAD) return;
    int k = (int)(i % XPAD);
    long long r = i / XPAD;
    int t = (int)(r % TN_); r /= TN_;
    int b = (int)(r % BN_);
    int inp = (int)(r / BN_);
    float v = 0.0f;
    if (k < DN_) {
        const float* src = inp ? hyp : prem;
        v = src[((long long)b * TN_ + t) * DN_ + k];
    }
    __half h = __float2half(v);
    g_xhi[i] = h;
    g_xlo[i] = __float2half(v - __half2float(h));
}

struct WPtrs { const float* wx[4]; const float* wh[4]; const float* bias[4]; };

__global__ void conv_w_kernel(WPtrs wp) {
    long long i = (long long)blockIdx.x * blockDim.x + threadIdx.x;
    if (i >= 4ll * FOURH * KPAD) return;
    int kp = (int)(i % KPAD);
    long long r = i / KPAD;
    int c   = (int)(r % FOURH);
    int seq = (int)(r / FOURH);
    int oc  = (c & 3) * HN_ + (c >> 2);     // gate-interleaved: col' = u*4+g
    float v = 0.0f;
    if (kp < DN_)        v = wp.wx[seq][(long long)kp * FOURH + oc];
    else if (kp >= XPAD) v = wp.wh[seq][(long long)(kp - XPAD) * FOURH + oc];
    __half h = __float2half(v);
    g_whi[i] = h;
    g_wlo[i] = __float2half(v - __half2float(h));
}

__global__ void conv_bias_kernel(WPtrs wp) {
    int i = blockIdx.x * blockDim.x + threadIdx.x;
    if (i >= 4 * FOURH) return;
    int c = i & (FOURH - 1);
    int seq = i >> 11;
    g_bp[i] = wp.bias[seq][(c & 3) * HN_ + (c >> 2)];
}

// ---------------------------------------------------------------------------
// Fused LSTM step via mma.sync (HMMA), fp16 hi/lo split, 3 products.
// Grid (16 n-tiles, 2 m-tiles, 4 seqs), 256 threads (8 warps: 2m x 4n).
// SMEM stage: Ah[128][64] | Al | Bh[128][64] | Bl, 16KB each, x2 stages.
#define ST_BYTES 65536
#define OFF_AL   16384
#define OFF_BH   32768
#define OFF_BL   49152
#define OFF_BIAS 131072
#define SMEM_TOTAL_STEP 131584

__global__ __launch_bounds__(256) void lstm_step_mma(const int* __restrict__ plen,
                                                     const int* __restrict__ hlen,
                                                     int s) {
    extern __shared__ char smem[];
    const uint32_t sbase = smem_u32(smem);
    const int tid  = threadIdx.x;
    const int lane = tid & 31;
    const int wid  = tid >> 5;
    const int warp_m = wid >> 2;       // 0..1
    const int warp_n = wid & 3;        // 0..3

    const int seq = blockIdx.z;
    const int rev = seq & 1;
    const int t   = rev ? (TN_ - 1 - s) : s;
    const int inp = seq >> 1;
    const int b0  = blockIdx.y * 128;
    const int n0  = blockIdx.x * 128;
    const int cur = s & 1;

    if (tid < 128)
        *(float*)(smem + OFF_BIAS + tid * 4) = g_bp[seq * FOURH + n0 + tid];

    const long hin_base  = ((long)cur * 4 + seq) * (BN_ * HN_);
    const long hout_base = ((long)(cur ^ 1) * 4 + seq) * (BN_ * HN_);

    // ---- chunk loader (cp.async) -----------------------------------------
    auto load_chunk = [&](int k, int p) {
        const uint32_t st = sbase + (p ? ST_BYTES : 0);
        const bool isx = (k < 5);
        const int k0 = k * 64;
        #pragma unroll
        for (int j = 0; j < 4; j++) {           // A: hi + lo
            int idx = tid + 256 * j;
            int row = idx >> 3;
            int seg = idx & 7;
            int kk  = k0 + seg * 8;
            long base;
            if (isx) base = ((long)(inp * BN_ + b0 + row) * TN_ + t) * XPAD + kk;
            else     base = hin_base + (long)(b0 + row) * HN_ + (kk - XPAD);
            uint32_t dst = st + ((row * 8 + (seg ^ (row & 7))) << 4);
            cp16(dst,          isx ? (const void*)(g_xhi + base) : (const void*)(g_hhi + base));
            cp16(dst + OFF_AL, isx ? (const void*)(g_xlo + base) : (const void*)(g_hlo + base));
        }
        #pragma unroll
        for (int j = 0; j < 4; j++) {           // B: hi + lo
            int idx = tid + 256 * j;
            int row = idx >> 3;
            int seg = idx & 7;
            int kk  = k0 + seg * 8;
            long base = ((long)seq * FOURH + n0 + row) * KPAD + kk;
            uint32_t dst = st + OFF_BH + ((row * 8 + (seg ^ (row & 7))) << 4);
            cp16(dst,         g_whi + base);
            cp16(dst + 16384, g_wlo + base);
        }
        CP_COMMIT();
    };

    // accumulators [mi][ni][4]
    float acc[4][4][4];
    #pragma unroll
    for (int mi = 0; mi < 4; mi++)
        #pragma unroll
        for (int ni = 0; ni < 4; ni++)
            #pragma unroll
            for (int q = 0; q < 4; q++) acc[mi][ni][q] = 0.0f;

    // per-lane ldmatrix row invariants
    int arowb[4], arowx[4];
    #pragma unroll
    for (int mi = 0; mi < 4; mi++) {
        int r = warp_m * 64 + mi * 16 + (lane & 15);
        arowb[mi] = r * 128;
        arowx[mi] = r & 7;
    }
    int brow[2], browx[2];
    #pragma unroll
    for (int np = 0; np < 2; np++) {
        int n = warp_n * 32 + np * 16 + ((lane >> 4) << 3) + (lane & 7);
        brow[np]  = n * 128;
        browx[np] = n & 7;
    }
    const int asel = lane >> 4;          // 0/1 -> k or k+8 half for A
    const int bsel = (lane >> 3) & 1;    // 0/1 -> k or k+8 half for B

    load_chunk(0, 0);

    for (int k = 0; k < NCHUNK; k++) {
        const int p = k & 1;
        if (k + 1 < NCHUNK) load_chunk(k + 1, p ^ 1);
        if (k + 1 < NCHUNK) CP_WAIT(1); else CP_WAIT(0);
        __syncthreads();

        const uint32_t st = sbase + (p ? ST_BYTES : 0);
        #pragma unroll
        for (int kk = 0; kk < 4; kk++) {
            uint32_t ah[4][4], al[4][4];
            #pragma unroll
            for (int mi = 0; mi < 4; mi++) {
                int seg = 2 * kk + asel;
                uint32_t off = arowb[mi] + ((seg ^ arowx[mi]) << 4);
                LDSM_X4(ah[mi][0], ah[mi][1], ah[mi][2], ah[mi][3], st + off);
                LDSM_X4(al[mi][0], al[mi][1], al[mi][2], al[mi][3], st + OFF_AL + off);
            }
            uint32_t bh[2][4], bl[2][4];
            #pragma unroll
            for (int np = 0; np < 2; np++) {
                int seg = 2 * kk + bsel;
                uint32_t off = brow[np] + ((seg ^ browx[np]) << 4);
                LDSM_X4(bh[np][0], bh[np][1], bh[np][2], bh[np][3], st + OFF_BH + off);
                LDSM_X4(bl[np][0], bl[np][1], bl[np][2], bl[np][3], st + OFF_BL + off);
            }
            #pragma unroll
            for (int mi = 0; mi < 4; mi++)
                #pragma unroll
                for (int np = 0; np < 2; np++)
                    #pragma unroll
                    for (int h = 0; h < 2; h++) {
                        int ni = np * 2 + h;
                        uint32_t bhf[2] = { bh[np][2 * h], bh[np][2 * h + 1] };
                        uint32_t blf[2] = { bl[np][2 * h], bl[np][2 * h + 1] };
                        MMA16816(acc[mi][ni], ah[mi], bhf);
                        MMA16816(acc[mi][ni], ah[mi], blf);
                        MMA16816(acc[mi][ni], al[mi], bhf);
                    }
        }
        __syncthreads();
    }

    // ---- epilogue: gates + masked state update ---------------------------
    const int* __restrict__ len = (seq < 2) ? plen : hlen;
    const float* bias_s = (const float*)(smem + OFF_BIAS);
    const bool amain = ((lane & 1) == 0);

    #pragma unroll
    for (int mi = 0; mi < 4; mi++) {
        #pragma unroll
        for (int ni = 0; ni < 4; ni++) {
            int col_local = warp_n * 32 + ni * 8 + 2 * (lane & 3);
            float v0 = acc[mi][ni][0] + bias_s[col_local];
            float v1 = acc[mi][ni][1] + bias_s[col_local + 1];
            float v2 = acc[mi][ni][2] + bias_s[col_local];
            float v3 = acc[mi][ni][3] + bias_s[col_local + 1];
            float p0 = __shfl_xor_sync(0xffffffffu, v0, 1);
            float p1 = __shfl_xor_sync(0xffffffffu, v1, 1);
            float p2 = __shfl_xor_sync(0xffffffffu, v2, 1);
            float p3 = __shfl_xor_sync(0xffffffffu, v3, 1);
            if (amain) {
                int u = (n0 + col_local) >> 2;
                #pragma unroll
                for (int rh = 0; rh < 2; rh++) {
                    int b = b0 + warp_m * 64 + mi * 16 + (lane >> 2) + rh * 8;
                    float iv = rh ? v2 : v0;
                    float jv = rh ? v3 : v1;
                    float fv = rh ? p2 : p0;
                    float ov = rh ? p3 : p1;
                    bool m = (t < len[b]);
                    long hidx = (long)b * HN_ + u;
                    float c_old = g_c[seq][b][u];
                    float nc = c_old * sigmoidf_(fv + 1.0f) + sigmoidf_(iv) * tanhf(jv);
                    float nh = tanhf(nc) * sigmoidf_(ov);
                    float cw = m ? nc : c_old;
                    g_c[seq][b][u] = cw;
                    __half hh, hl;
                    if (m) {
                        hh = __float2half(nh);
                        hl = __float2half(nh - __half2float(hh));
                    } else {
                        hh = g_hhi[hin_base + hidx];
                        hl = g_hlo[hin_base + hidx];
                    }
                    g_hhi[hout_base + hidx] = hh;
                    g_hlo[hout_base + hidx] = hl;
                }
            }
        }
    }
}

// ---------------------------------------------------------------------------
// MLP head (fp32)
__global__ void gather_x_kernel() {
    int i = blockIdx.x * blockDim.x + threadIdx.x;
    if (i >= BN_ * FOURH) return;
    int b   = i >> 11;
    int col = i & 2047;
    g_x[i] = g_c[col >> 9][b][col & 511];
}

#define BMT 64
#define BUT 64
#define KT  16
__global__ __launch_bounds__(256) void mlp_gemm_kernel(const float* __restrict__ W,
                                                       const float* __restrict__ bias,
                                                       int layer) {
    const float* A; float* C; int K, N;
    if (layer == 1)      { A = g_x;  C = g_m1; K = 2048; N = 1024; }
    else if (layer == 2) { A = g_m1; C = g_m2; K = 1024; N = 1024; }
    else                 { A = g_m2; C = g_m3; K = 1024; N = 1024; }

    const int m0 = blockIdx.y * BMT;
    const int n0 = blockIdx.x * BUT;
    __shared__ float As[KT][BMT];
    __shared__ float Bs[KT][BUT];
    const int tid = threadIdx.x;
    const int r0  = (tid >> 4) * 4;
    const int nt0 = (tid & 15) * 4;

    float acc[4][4];
    #pragma unroll
    for (int r = 0; r < 4; r++)
        #pragma unroll
        for (int u = 0; u < 4; u++) acc[r][u] = 0.0f;

    for (int k0 = 0; k0 < K; k0 += KT) {
        {
            int r  = tid >> 2;
            int kq = (tid & 3) * 4;
            #pragma unroll
            for (int i = 0; i < 4; i++)
                As[kq + i][r] = A[(m0 + r) * K + k0 + kq + i];
        }
        {
            int kk = tid >> 4;
            int uu = (tid & 15) * 4;
            *(float4*)&Bs[kk][uu] = *(const float4*)(W + (k0 + kk) * N + n0 + uu);
        }
        __syncthreads();
        #pragma unroll
        for (int kk = 0; kk < KT; kk++) {
            float4 a4 = *(const float4*)&As[kk][r0];
            float4 b4 = *(const float4*)&Bs[kk][nt0];
            float av[4] = {a4.x, a4.y, a4.z, a4.w};
            float bv[4] = {b4.x, b4.y, b4.z, b4.w};
            #pragma unroll
            for (int r = 0; r < 4; r++)
                #pragma unroll
                for (int u = 0; u < 4; u++)
                    acc[r][u] = fmaf(av[r], bv[u], acc[r][u]);
        }
        __syncthreads();
    }
    #pragma unroll
    for (int r = 0; r < 4; r++)
        #pragma unroll
        for (int u = 0; u < 4; u++) {
            int n = n0 + nt0 + u;
            C[(m0 + r0 + r) * N + n] = tanhf(acc[r][u] + bias[n]);
        }
}

__global__ void final_logits_kernel(const float* __restrict__ W4,
                                    const float* __restrict__ b4,
                                    float* __restrict__ out) {
    int b    = blockIdx.x;
    int w    = threadIdx.x >> 5;
    int lane = threadIdx.x & 31;
    if (w >= 3) return;
    float sum = 0.0f;
    for (int k = lane; k < 1024; k += 32)
        sum += g_m3[b * 1024 + k] * W4[k * 3 + w];
    #pragma unroll
    for (int off = 16; off; off >>= 1)
        sum += __shfl_down_sync(0xffffffff, sum, off);
    if (lane == 0) out[b * 3 + w] = sum + b4[w];
}

// ---------------------------------------------------------------------------
extern "C" void kernel_launch(void* const* d_in, const int* in_sizes, int n_in,
                              void* d_out, int out_size) {
    const float* premises   = (const float*)d_in[0];
    const float* hypotheses = (const float*)d_in[1];
    const int*   plen       = (const int*)d_in[2];
    const int*   hlen       = (const int*)d_in[3];

    WPtrs wp;
    for (int i = 0; i < 4; i++) {
        wp.wx[i]   = (const float*)d_in[4 + 3 * i + 0];
        wp.wh[i]   = (const float*)d_in[4 + 3 * i + 1];
        wp.bias[i] = (const float*)d_in[4 + 3 * i + 2];
    }
    const float* W1 = (const float*)d_in[16];
    const float* b1 = (const float*)d_in[17];
    const float* W2 = (const float*)d_in[18];
    const float* b2 = (const float*)d_in[19];
    const float* W3 = (const float*)d_in[20];
    const float* b3 = (const float*)d_in[21];
    const float* W4 = (const float*)d_in[22];
    const float* b4 = (const float*)d_in[23];
    float* out = (float*)d_out;

    cudaFuncSetAttribute(lstm_step_mma, cudaFuncAttributeMaxDynamicSharedMemorySize,
                         SMEM_TOTAL_STEP);

    // one-time preprocessing
    zero_state_kernel<<<(2 * 4 * BN_ * HN_ + 255) / 256, 256>>>();
    {
        long long n = 2ll * BN_ * TN_ * XPAD;
        conv_x_kernel<<<(unsigned)((n + 255) / 256), 256>>>(premises, hypotheses);
    }
    {
        long long n = 4ll * FOURH * KPAD;
        conv_w_kernel<<<(unsigned)((n + 255) / 256), 256>>>(wp);
    }
    conv_bias_kernel<<<(4 * FOURH + 255) / 256, 256>>>(wp);

    // recurrence
    dim3 grid(16, 2, 4);
    for (int s = 0; s < TN_; s++)
        lstm_step_mma<<<grid, 256, SMEM_TOTAL_STEP>>>(plen, hlen, s);

    // MLP head
    gather_x_kernel<<<(BN_ * FOURH + 255) / 256, 256>>>();
    mlp_gemm_kernel<<<dim3(1024 / BUT, BN_ / BMT), 256>>>(W1, b1, 1);
    mlp_gemm_kernel<<<dim3(1024 / BUT, BN_ / BMT), 256>>>(W2, b2, 2);
    mlp_gemm_kernel<<<dim3(1024 / BUT, BN_ / BMT), 256>>>(W3, b3, 3);
    final_logits_kernel<<<BN_, 96>>>(W4, b4, out);
}